// round 15
// baseline (speedup 1.0000x reference)
#include <cuda_runtime.h>
#include <cuda_fp16.h>
#include <cstdint>
#include <math.h>

#define BB 128
#define SS 1000
#define HH 256
#define MM (BB*SS)        // 128000

// ------------------------- device scratch (no allocs) -----------------------
__device__ float g_hnew[BB*HH];
__device__ float g_ph[BB*3*HH];           // attention hidden-part bias [B,768]
__device__ float g_scores[MM];
__device__ float g_ctxp[BB*16*HH];        // context partials
__device__ float g_pc[BB*2*HH];           // pointer ctx-part bias [B,512]
__device__ float g_scores2[MM];
__device__ int   g_ctr[BB];               // finisher counters (self-resetting)
__device__ __half g_W1[768*512];          // attn_W cols [0,512), fp16, [N][K]
__device__ __half g_W2[512*256];          // dec_W  cols [0,256), fp16, [N][K]

__device__ __forceinline__ float sigmoidf_(float x){ return 1.0f/(1.0f+expf(-x)); }

__device__ __forceinline__ float fast_tanh(float x){
    x = fminf(fmaxf(x, -15.0f), 15.0f);
    float e = __expf(2.0f*x);
    return __fdividef(e - 1.0f, e + 1.0f);
}

__device__ __forceinline__ uint32_t smem_to_u32(const void* p) {
    uint32_t a;
    asm("{ .reg .u64 t; cvta.to.shared.u64 t, %1; cvt.u32.u64 %0, t; }" : "=r"(a) : "l"(p));
    return a;
}

__device__ __forceinline__ void ldsm4(uint32_t& r0, uint32_t& r1, uint32_t& r2, uint32_t& r3,
                                      uint32_t addr) {
    asm volatile("ldmatrix.sync.aligned.m8n8.x4.shared.b16 {%0,%1,%2,%3}, [%4];"
                 : "=r"(r0), "=r"(r1), "=r"(r2), "=r"(r3) : "r"(addr));
}

__device__ __forceinline__ void mma_f16(float* c, uint32_t a0, uint32_t a1, uint32_t a2,
                                        uint32_t a3, uint32_t b0, uint32_t b1) {
    asm volatile(
        "mma.sync.aligned.m16n8k16.row.col.f32.f16.f16.f32 "
        "{%0,%1,%2,%3},{%4,%5,%6,%7},{%8,%9},{%0,%1,%2,%3};"
        : "+f"(c[0]), "+f"(c[1]), "+f"(c[2]), "+f"(c[3])
        : "r"(a0), "r"(a1), "r"(a2), "r"(a3), "r"(b0), "r"(b1));
}

__device__ __forceinline__ void cpasync16(uint32_t dst, const void* src) {
    asm volatile("cp.async.cg.shared.global [%0], [%1], 16;" :: "r"(dst), "l"(src));
}

// SMEM layout (dynamic, byte offsets) — compact header (no bias cache)
#define OFF_V   0                         // NTOT floats (<=3072B)
#define OFF_SC  3072                      // 256 floats
#define OFF_A   4096                      // A fp16, 64*KTOT*2 bytes

// ---------------------------------------------------------------------------
// Fused score GEMM on HMMA (mma.sync fp16, single-term) — R14 compute core,
// NSTAGE-deep cp.async ring (128n x 32k chunks, 8KB/stage, SW64 rows),
// ONE __syncthreads per chunk, bias read from L2 in the epilogue:
//   score[m] = sum_n v[n] * tanh( sum_k A[m,k]*W[n,k] + bias[b(m),n] )
// BM=64/CTA, 8 warps (2m x 4n), warp tile 32m x 32n.
// GEMM1: 5 stages (dist-4), occ 2.  GEMM2: 4 stages (dist-3), occ 3.
// ---------------------------------------------------------------------------
template<int NTOT, int KTOT, int SEL, int NSTAGE, int MAXBPSM>
__global__ void __launch_bounds__(256, MAXBPSM) score_gemm_mma(
    const float* __restrict__ A1, const float* __restrict__ A2,
    const float* __restrict__ v)
{
    constexpr int NTILES  = NTOT / 128;
    constexpr int KCHUNKS = KTOT / 32;           // 32k per chunk
    constexpr int TOTAL   = NTILES * KCHUNKS;
    constexpr int ASZ     = 64 * KTOT * 2;       // A bytes (fp16)
    constexpr int OFFW    = OFF_A + ASZ;         // W ring: NSTAGE x 8KB

    const __half* __restrict__ Wp  = SEL ? g_W2 : g_W1;
    const float* __restrict__ bias = SEL ? g_pc : g_ph;
    float* __restrict__ outS       = SEL ? g_scores2 : g_scores;

    extern __shared__ char smem[];
    const uint32_t su = smem_to_u32(smem);
    float* vs  = (float*)(smem + OFF_V);
    float* scp = (float*)(smem + OFF_SC);

    const int tid  = threadIdx.x;
    const int lane = tid & 31;
    const int wrp  = tid >> 5;
    const int wm   = wrp & 1;          // m-half (32 rows)
    const int wn   = wrp >> 1;         // n-quarter (32 cols of the 128 tile)
    const int mBase = blockIdx.x * 64;
    const int b0 = mBase / SS;
    const int b1 = (mBase + 63) / SS;

    // --- W chunk issuer: 128n x 32k fp16, 64B rows, SW64, via cp.async (8KB) ---
    auto issue = [&](int chunk, int stage) {
        int nt = chunk / KCHUNKS, kc = chunk - nt*KCHUNKS;
        uint32_t dst = su + OFFW + (uint32_t)stage * 8192u;
        int nb = nt * 128, kb = kc * 32;
        #pragma unroll
        for (int i = 0; i < 2; i++) {
            int id = tid*2 + i;            // 0..511
            int n  = id >> 2, kseg = id & 3;
            uint32_t o  = (uint32_t)n * 64u + (uint32_t)kseg * 16u;
            uint32_t sw = o ^ ((o >> 3) & 0x30u);
            cpasync16(dst + sw, Wp + (size_t)(nb + n) * KTOT + kb + kseg*8);
        }
        asm volatile("cp.async.commit_group;" ::: "memory");
    };

    // prime NSTAGE-1 stages, overlapping with A conversion below
    #pragma unroll
    for (int s = 0; s < NSTAGE-1; s++) issue(s, s);

    // v into smem
    for (int i = tid; i < NTOT; i += 256) vs[i] = v[i];

    // --- convert A (fp32) -> fp16 into SW128-swizzled smem, full K ---
    {
        constexpr int K4 = KTOT / 4;
        constexpr int ITERS = 64 * K4 / 256;
        #pragma unroll
        for (int it = 0; it < ITERS; it++) {
            int id  = it*256 + tid;
            int row = id / K4;
            int k   = (id - row*K4) * 4;
            const float* src;
            if (KTOT > 256 && k >= 256) src = A2 + (size_t)(mBase + row)*HH + (k - 256);
            else                        src = A1 + (size_t)(mBase + row)*HH + k;
            float4 a4 = *reinterpret_cast<const float4*>(src);
            __half2 h01 = __floats2half2_rn(a4.x, a4.y);
            __half2 h23 = __floats2half2_rn(a4.z, a4.w);
            uint32_t sw = ((uint32_t)(((k >> 3) ^ (row & 7)) << 4)) + ((uint32_t)(k & 4) << 1);
            uint32_t ro = (uint32_t)row * (KTOT*2);
            *reinterpret_cast<uint2*>(smem + OFF_A + ro + sw) =
                make_uint2(*reinterpret_cast<uint32_t*>(&h01),
                           *reinterpret_cast<uint32_t*>(&h23));
        }
    }
    // first loop barrier publishes A stores + stage-0 data

    // per-thread lane-constant addressing
    const int rowA0 = wm*32 + (lane & 15);
    const int ra7   = rowA0 & 7;
    const uint32_t aRow0 = su + OFF_A + (uint32_t)rowA0 * (KTOT*2);
    const uint32_t aRow1 = aRow0 + 16u * (KTOT*2);
    const int k8a   = (lane >> 4) * 8;
    // W ldmatrix rows for 2 n16-groups (32 n per warp), SW64 on 64B rows.
    const int nwl = ((lane >> 4) << 3) + (lane & 7);
    const uint32_t kb2 = ((uint32_t)((lane >> 3) & 1)) * 16u;
    uint32_t swb[2];
    #pragma unroll
    for (int g = 0; g < 2; g++) {
        uint32_t o = (uint32_t)(wn*32 + g*16 + nwl) * 64u + kb2;
        swb[g] = o ^ ((o >> 3) & 0x30u);
    }

    // epilogue rows: 4 per thread; per-row bias pointer (L2 reads, no smem)
    const int rb = wm*32 + (lane >> 2);
    int rr[4]; const float* bq[4];
    #pragma unroll
    for (int q = 0; q < 4; q++) {
        rr[q] = rb + (q & 1)*8 + (q >> 1)*16;
        int sel = ((mBase + rr[q]) / SS != b0) ? 1 : 0;
        bq[q] = bias + (size_t)(sel ? b1 : b0) * NTOT;
    }

    float pr[4] = {0.f, 0.f, 0.f, 0.f};
    int ch = 0;
    int stComp = 0;                 // stage of chunk ch
    int stIss  = NSTAGE - 1;        // stage for next issue

    for (int nt = 0; nt < NTILES; nt++) {
        float c[2][4][4];
        #pragma unroll
        for (int mi = 0; mi < 2; mi++)
            #pragma unroll
            for (int g = 0; g < 4; g++)
                #pragma unroll
                for (int j = 0; j < 4; j++) c[mi][g][j] = 0.f;

        for (int kc = 0; kc < KCHUNKS; kc++, ch++) {
            // wait for chunk ch (immediate-operand forms, tail-tightened)
            if (NSTAGE == 5) {
                if (ch < TOTAL-3)       { asm volatile("cp.async.wait_group 3;" ::: "memory"); }
                else if (ch == TOTAL-3) { asm volatile("cp.async.wait_group 2;" ::: "memory"); }
                else if (ch == TOTAL-2) { asm volatile("cp.async.wait_group 1;" ::: "memory"); }
                else                    { asm volatile("cp.async.wait_group 0;" ::: "memory"); }
            } else {
                if (ch < TOTAL-2)       { asm volatile("cp.async.wait_group 2;" ::: "memory"); }
                else if (ch == TOTAL-2) { asm volatile("cp.async.wait_group 1;" ::: "memory"); }
                else                    { asm volatile("cp.async.wait_group 0;" ::: "memory"); }
            }
            __syncthreads();   // publishes chunk ch; proves ch-1 fully read
            if (ch + NSTAGE - 1 < TOTAL) {
                issue(ch + NSTAGE - 1, stIss);
                stIss++; if (stIss == NSTAGE) stIss = 0;
            }

            const uint32_t Wb = su + OFFW + (uint32_t)stComp * 8192u;
            stComp++; if (stComp == NSTAGE) stComp = 0;

            #pragma unroll
            for (int ks = 0; ks < 2; ks++) {
                int kk = kc*32 + ks*16 + k8a;
                uint32_t aoff = (uint32_t)(((kk >> 3) ^ ra7) << 4);
                uint32_t a00,a01,a02,a03, a10,a11,a12,a13;
                ldsm4(a00,a01,a02,a03, aRow0 + aoff);
                ldsm4(a10,a11,a12,a13, aRow1 + aoff);

                uint32_t b00,b01,b02,b03, b10,b11,b12,b13;
                ldsm4(b00,b01,b02,b03, Wb + (swb[0] ^ ((uint32_t)ks * 32u)));
                ldsm4(b10,b11,b12,b13, Wb + (swb[1] ^ ((uint32_t)ks * 32u)));

                mma_f16(c[0][0], a00,a01,a02,a03, b00,b01);
                mma_f16(c[0][1], a00,a01,a02,a03, b02,b03);
                mma_f16(c[0][2], a00,a01,a02,a03, b10,b11);
                mma_f16(c[0][3], a00,a01,a02,a03, b12,b13);
                mma_f16(c[1][0], a10,a11,a12,a13, b00,b01);
                mma_f16(c[1][1], a10,a11,a12,a13, b02,b03);
                mma_f16(c[1][2], a10,a11,a12,a13, b10,b11);
                mma_f16(c[1][3], a10,a11,a12,a13, b12,b13);
            }
        }

        // epilogue for this 128-col n-tile (bias from L2)
        int nbb = nt*128 + wn*32;
        #pragma unroll
        for (int g = 0; g < 4; g++) {
            int n0 = nbb + (g & 1)*8 + (g >> 1)*16 + (lane & 3)*2;
            float v0 = vs[n0], v1 = vs[n0+1];
            #pragma unroll
            for (int mi = 0; mi < 2; mi++) {
                int q0 = mi*2;
                pr[q0]   += v0 * fast_tanh(c[mi][g][0] + __ldg(bq[q0]   + n0))
                          + v1 * fast_tanh(c[mi][g][1] + __ldg(bq[q0]   + n0 + 1));
                pr[q0+1] += v0 * fast_tanh(c[mi][g][2] + __ldg(bq[q0+1] + n0))
                          + v1 * fast_tanh(c[mi][g][3] + __ldg(bq[q0+1] + n0 + 1));
            }
        }
    }

    // reduce quad, then combine the 4 n-warp banks
    #pragma unroll
    for (int q = 0; q < 4; q++) {
        pr[q] += __shfl_xor_sync(0xffffffffu, pr[q], 1);
        pr[q] += __shfl_xor_sync(0xffffffffu, pr[q], 2);
    }
    if ((lane & 3) == 0) {
        #pragma unroll
        for (int q = 0; q < 4; q++) scp[wn*64 + rr[q]] = pr[q];
    }
    __syncthreads();
    if (tid < 64)
        outS[mBase + tid] = scp[tid] + scp[64 + tid] + scp[128 + tid] + scp[192 + tid];
}

// ---------------------------------------------------------------------------
// Weight conversion to fp16, transposed to [N][K] k-contiguous
// ---------------------------------------------------------------------------
__global__ void k_convW(const float* __restrict__ attnW, const float* __restrict__ decW)
{
    int i = blockIdx.x * 256 + threadIdx.x;
    if (i < 768*512) {
        int j = i / 512, k = i % 512;
        g_W1[i] = __float2half_rn(attnW[j*768 + k]);
    } else {
        int i2 = i - 768*512;
        int j = i2 / 256, k = i2 % 256;
        g_W2[i2] = __float2half_rn(decW[j*512 + k]);
    }
}

// ---------------------------------------------------------------------------
// K1: embed + GRU cell + attention hidden-part bias (merged)
// ---------------------------------------------------------------------------
__global__ void k_gru(const float* __restrict__ din, const float* __restrict__ lasth,
                      const float* __restrict__ embW, const float* __restrict__ embB,
                      const float* __restrict__ Wih, const float* __restrict__ Whh,
                      const float* __restrict__ bih, const float* __restrict__ bhh,
                      const float* __restrict__ attnW,
                      float* __restrict__ outHidden)
{
    __shared__ float emb[HH], hp[HH], gx[3*HH], gh[3*HH], hs[HH];
    int b = blockIdx.x, t = threadIdx.x;
    float d0 = din[b*2+0], d1 = din[b*2+1];
    emb[t] = d0*embW[t*2+0] + d1*embW[t*2+1] + embB[t];
    hp[t]  = lasth[b*HH + t];
    __syncthreads();
    int warp = t >> 5, lane = t & 31;
    for (int j = warp; j < 3*HH; j += 8) {
        const float* wi = Wih + (size_t)j*HH;
        const float* wh = Whh + (size_t)j*HH;
        float sx = 0.f, sh = 0.f;
        #pragma unroll
        for (int i = 0; i < 8; i++) {
            int k = lane + 32*i;
            sx += wi[k]*emb[k]; sh += wh[k]*hp[k];
        }
        #pragma unroll
        for (int o = 16; o; o >>= 1) {
            sx += __shfl_xor_sync(0xffffffffu, sx, o);
            sh += __shfl_xor_sync(0xffffffffu, sh, o);
        }
        if (lane == 0) { gx[j] = sx + bih[j]; gh[j] = sh + bhh[j]; }
    }
    __syncthreads();
    float r = sigmoidf_(gx[t]        + gh[t]);
    float z = sigmoidf_(gx[HH + t]   + gh[HH + t]);
    float n = tanhf    (gx[2*HH + t] + r*gh[2*HH + t]);
    float h = (1.0f - z)*n + z*hp[t];
    g_hnew[b*HH + t]    = h;
    outHidden[b*HH + t] = h;
    hs[t] = h;
    __syncthreads();
    for (int j = warp; j < 3*HH; j += 8) {
        const float* w = attnW + (size_t)j*(3*HH) + 2*HH;
        float s = 0.f;
        #pragma unroll
        for (int i = 0; i < 8; i++) { int k = lane + 32*i; s += w[k]*hs[k]; }
        #pragma unroll
        for (int o = 16; o; o >>= 1) s += __shfl_xor_sync(0xffffffffu, s, o);
        if (lane == 0) g_ph[b*(3*HH) + j] = s;
    }
}

__device__ __forceinline__ float blockReduce(float val, float* red, bool isMax)
{
    __syncthreads();
    int lane = threadIdx.x & 31, w = threadIdx.x >> 5;
    #pragma unroll
    for (int o = 16; o; o >>= 1) {
        float u = __shfl_xor_sync(0xffffffffu, val, o);
        val = isMax ? fmaxf(val, u) : val + u;
    }
    if (lane == 0) red[w] = val;
    __syncthreads();
    if (w == 0) {
        val = (lane < 8) ? red[lane] : (isMax ? -1e30f : 0.f);
        #pragma unroll
        for (int o = 16; o; o >>= 1) {
            float u = __shfl_xor_sync(0xffffffffu, val, o);
            val = isMax ? fmaxf(val, u) : val + u;
        }
        if (lane == 0) red[0] = val;
    }
    __syncthreads();
    return red[0];
}

// ---------------------------------------------------------------------------
// K3: softmax (recomputed locally) + context partial + fused finisher that
// combines partials and computes the pointer ctx-part bias. grid (B, 16).
// ---------------------------------------------------------------------------
__global__ void k_ctx(const float* __restrict__ stat, const float* __restrict__ decW)
{
    __shared__ float at[SS];
    __shared__ float red[32];
    __shared__ float ctx[HH];
    __shared__ int oldc;
    int b = blockIdx.x, p = blockIdx.y, t = threadIdx.x;

    float mx = -1e30f;
    for (int s = t; s < SS; s += 256) { float x = g_scores[b*SS+s]; at[s]=x; mx=fmaxf(mx,x); }
    mx = blockReduce(mx, red, true);
    float sum = 0.f;
    for (int s = t; s < SS; s += 256) { float e = __expf(at[s]-mx); at[s]=e; sum+=e; }
    sum = blockReduce(sum, red, false);
    float inv = 1.0f / sum;

    // slice: p<8 -> 63 rows from 63p; p>=8 -> 62 rows from 504+62(p-8)
    int s0  = (p < 8) ? 63*p : 504 + 62*(p - 8);
    int cnt = (p < 8) ? 63 : 62;
    const float* sb = stat + ((size_t)b*SS + s0)*HH;
    float acc = 0.f;
    #pragma unroll 8
    for (int s = 0; s < 62; s++) acc += at[s0 + s]*sb[(size_t)s*HH + t];
    if (cnt == 63) acc += at[s0 + 62]*sb[(size_t)62*HH + t];
    g_ctxp[(b*16 + p)*HH + t] = acc * inv;

    // finisher election
    __threadfence();
    __syncthreads();
    if (t == 0) oldc = atomicAdd(&g_ctr[b], 1);
    __syncthreads();
    if (oldc != 15) return;

    // last block for this b: combine partials + dec_W matvec
    __threadfence();
    float a2 = 0.f;
    #pragma unroll
    for (int q = 0; q < 16; q++) a2 += g_ctxp[(b*16 + q)*HH + t];
    ctx[t] = a2;
    if (t == 0) g_ctr[b] = 0;     // reset for next graph replay
    __syncthreads();
    int warp = t >> 5, lane = t & 31;
    for (int j = warp; j < 2*HH; j += 8) {
        const float* w = decW + (size_t)j*(2*HH) + HH;
        float s = 0.f;
        #pragma unroll
        for (int i = 0; i < 8; i++) { int k = lane + 32*i; s += w[k]*ctx[k]; }
        #pragma unroll
        for (int o = 16; o; o >>= 1) s += __shfl_xor_sync(0xffffffffu, s, o);
        if (lane == 0) g_pc[b*(2*HH) + j] = s;
    }
}

// final softmax into d_out[0 : B*S)
__global__ void k_out(float* __restrict__ out)
{
    __shared__ float at[SS];
    __shared__ float red[32];
    int b = blockIdx.x, t = threadIdx.x;
    float mx = -1e30f;
    for (int s = t; s < SS; s += 256) { float x = g_scores2[b*SS+s]; at[s]=x; mx=fmaxf(mx,x); }
    mx = blockReduce(mx, red, true);
    float sum = 0.f;
    for (int s = t; s < SS; s += 256) { float e = expf(at[s]-mx); at[s]=e; sum+=e; }
    sum = blockReduce(sum, red, false);
    float inv = 1.0f/sum;
    for (int s = t; s < SS; s += 256) out[b*SS+s] = at[s]*inv;
}

// ---------------------------------------------------------------------------
extern "C" void kernel_launch(void* const* d_in, const int* in_sizes, int n_in,
                              void* d_out, int out_size)
{
    (void)in_sizes; (void)n_in; (void)out_size;
    const float* din   = (const float*)d_in[0];
    const float* lasth = (const float*)d_in[1];
    const float* stat  = (const float*)d_in[2];
    const float* dyn   = (const float*)d_in[3];
    const float* embW  = (const float*)d_in[4];
    const float* embB  = (const float*)d_in[5];
    const float* Wih   = (const float*)d_in[6];
    const float* Whh   = (const float*)d_in[7];
    const float* bih   = (const float*)d_in[8];
    const float* bhh   = (const float*)d_in[9];
    const float* attnW = (const float*)d_in[10];
    const float* attnV = (const float*)d_in[11];
    const float* decW  = (const float*)d_in[12];
    const float* decV  = (const float*)d_in[13];
    float* out = (float*)d_out;

    // GEMM1: 5 stages, occ 2: 4096 + 65536 + 40960 = 110592 (2x <= 228KB)
    // GEMM2: 4 stages, occ 3: 4096 + 32768 + 32768 =  69632 (3x <= 228KB)
    const int smem1 = OFF_A + (64*512*2) + 5*8192;
    const int smem2 = OFF_A + (64*256*2) + 4*8192;
    cudaFuncSetAttribute((const void*)score_gemm_mma<768,512,0,5,2>,
                         cudaFuncAttributeMaxDynamicSharedMemorySize, smem1);
    cudaFuncSetAttribute((const void*)score_gemm_mma<512,256,1,4,3>,
                         cudaFuncAttributeMaxDynamicSharedMemorySize, smem2);

    k_convW<<<2048, 256>>>(attnW, decW);
    k_gru<<<BB, 256>>>(din, lasth, embW, embB, Wih, Whh, bih, bhh, attnW, out + MM);
    score_gemm_mma<768,512,0,5,2><<<MM/64, 256, smem1>>>(stat, dyn, attnV);
    k_ctx<<<dim3(BB, 16), 256>>>(stat, decW);
    score_gemm_mma<512,256,1,4,3><<<MM/64, 256, smem2>>>(stat, stat, decV);
    k_out<<<BB, 256>>>(out);
}

// round 16
// speedup vs baseline: 1.0001x; 1.0001x over previous
#include <cuda_runtime.h>
#include <cuda_fp16.h>
#include <cstdint>
#include <math.h>

#define BB 128
#define SS 1000
#define HH 256
#define MM (BB*SS)        // 128000

// ------------------------- device scratch (no allocs) -----------------------
__device__ float g_hnew[BB*HH];
__device__ float g_ph[BB*3*HH];           // attention hidden-part bias [B,768]
__device__ float g_scores[MM];
__device__ float g_ctxp[BB*8*HH];         // context partials
__device__ float g_pc[BB*2*HH];           // pointer ctx-part bias [B,512]
__device__ float g_scores2[MM];
__device__ __half g_W1[768*512];          // attn_W cols [0,512), fp16, [N][K]
__device__ __half g_W2[512*256];          // dec_W  cols [0,256), fp16, [N][K]

__device__ __forceinline__ float sigmoidf_(float x){ return 1.0f/(1.0f+expf(-x)); }

__device__ __forceinline__ float fast_tanh(float x){
    x = fminf(fmaxf(x, -15.0f), 15.0f);
    float e = __expf(2.0f*x);
    return __fdividef(e - 1.0f, e + 1.0f);
}

__device__ __forceinline__ uint32_t smem_to_u32(const void* p) {
    uint32_t a;
    asm("{ .reg .u64 t; cvta.to.shared.u64 t, %1; cvt.u32.u64 %0, t; }" : "=r"(a) : "l"(p));
    return a;
}

__device__ __forceinline__ void ldsm4(uint32_t& r0, uint32_t& r1, uint32_t& r2, uint32_t& r3,
                                      uint32_t addr) {
    asm volatile("ldmatrix.sync.aligned.m8n8.x4.shared.b16 {%0,%1,%2,%3}, [%4];"
                 : "=r"(r0), "=r"(r1), "=r"(r2), "=r"(r3) : "r"(addr));
}

__device__ __forceinline__ void mma_f16(float* c, uint32_t a0, uint32_t a1, uint32_t a2,
                                        uint32_t a3, uint32_t b0, uint32_t b1) {
    asm volatile(
        "mma.sync.aligned.m16n8k16.row.col.f32.f16.f16.f32 "
        "{%0,%1,%2,%3},{%4,%5,%6,%7},{%8,%9},{%0,%1,%2,%3};"
        : "+f"(c[0]), "+f"(c[1]), "+f"(c[2]), "+f"(c[3])
        : "r"(a0), "r"(a1), "r"(a2), "r"(a3), "r"(b0), "r"(b1));
}

__device__ __forceinline__ void cpasync16(uint32_t dst, const void* src) {
    asm volatile("cp.async.cg.shared.global [%0], [%1], 16;" :: "r"(dst), "l"(src));
}

// SMEM layout (dynamic, byte offsets) — compact header (no bias cache)
#define OFF_V   0                         // NTOT floats (<=3072B)
#define OFF_SC  3072                      // 256 floats
#define OFF_A   4096                      // A fp16, 64*KTOT*2 bytes

// ---------------------------------------------------------------------------
// Fused score GEMM on HMMA (mma.sync fp16, single-term), NSTAGE-deep cp.async
// ring (128n x 32k chunks, 8KB/stage, SW64 rows), ONE __syncthreads per chunk,
// bias read from L2 in the epilogue:
//   score[m] = sum_n v[n] * tanh( sum_k A[m,k]*W[n,k] + bias[b(m),n] )
// BM=64/CTA, 8 warps (2m x 4n), warp tile 32m x 32n.
// GEMM1: 5 stages (dist-4), occ 2.  GEMM2: 4 stages (dist-3), occ 3.
// ---------------------------------------------------------------------------
template<int NTOT, int KTOT, int SEL, int NSTAGE, int MAXBPSM>
__global__ void __launch_bounds__(256, MAXBPSM) score_gemm_mma(
    const float* __restrict__ A1, const float* __restrict__ A2,
    const float* __restrict__ v)
{
    constexpr int NTILES  = NTOT / 128;
    constexpr int KCHUNKS = KTOT / 32;           // 32k per chunk
    constexpr int TOTAL   = NTILES * KCHUNKS;
    constexpr int ASZ     = 64 * KTOT * 2;       // A bytes (fp16)
    constexpr int OFFW    = OFF_A + ASZ;         // W ring: NSTAGE x 8KB

    const __half* __restrict__ Wp  = SEL ? g_W2 : g_W1;
    const float* __restrict__ bias = SEL ? g_pc : g_ph;
    float* __restrict__ outS       = SEL ? g_scores2 : g_scores;

    extern __shared__ char smem[];
    const uint32_t su = smem_to_u32(smem);
    float* vs  = (float*)(smem + OFF_V);
    float* scp = (float*)(smem + OFF_SC);

    const int tid  = threadIdx.x;
    const int lane = tid & 31;
    const int wrp  = tid >> 5;
    const int wm   = wrp & 1;          // m-half (32 rows)
    const int wn   = wrp >> 1;         // n-quarter (32 cols of the 128 tile)
    const int mBase = blockIdx.x * 64;
    const int b0 = mBase / SS;
    const int b1 = (mBase + 63) / SS;

    // --- W chunk issuer: 128n x 32k fp16, 64B rows, SW64, via cp.async (8KB) ---
    auto issue = [&](int chunk, int stage) {
        int nt = chunk / KCHUNKS, kc = chunk - nt*KCHUNKS;
        uint32_t dst = su + OFFW + (uint32_t)stage * 8192u;
        int nb = nt * 128, kb = kc * 32;
        #pragma unroll
        for (int i = 0; i < 2; i++) {
            int id = tid*2 + i;            // 0..511
            int n  = id >> 2, kseg = id & 3;
            uint32_t o  = (uint32_t)n * 64u + (uint32_t)kseg * 16u;
            uint32_t sw = o ^ ((o >> 3) & 0x30u);
            cpasync16(dst + sw, Wp + (size_t)(nb + n) * KTOT + kb + kseg*8);
        }
        asm volatile("cp.async.commit_group;" ::: "memory");
    };

    // prime NSTAGE-1 stages, overlapping with A conversion below
    #pragma unroll
    for (int s = 0; s < NSTAGE-1; s++) issue(s, s);

    // v into smem
    for (int i = tid; i < NTOT; i += 256) vs[i] = v[i];

    // --- convert A (fp32) -> fp16 into SW128-swizzled smem, full K ---
    {
        constexpr int K4 = KTOT / 4;
        constexpr int ITERS = 64 * K4 / 256;
        #pragma unroll
        for (int it = 0; it < ITERS; it++) {
            int id  = it*256 + tid;
            int row = id / K4;
            int k   = (id - row*K4) * 4;
            const float* src;
            if (KTOT > 256 && k >= 256) src = A2 + (size_t)(mBase + row)*HH + (k - 256);
            else                        src = A1 + (size_t)(mBase + row)*HH + k;
            float4 a4 = *reinterpret_cast<const float4*>(src);
            __half2 h01 = __floats2half2_rn(a4.x, a4.y);
            __half2 h23 = __floats2half2_rn(a4.z, a4.w);
            uint32_t sw = ((uint32_t)(((k >> 3) ^ (row & 7)) << 4)) + ((uint32_t)(k & 4) << 1);
            uint32_t ro = (uint32_t)row * (KTOT*2);
            *reinterpret_cast<uint2*>(smem + OFF_A + ro + sw) =
                make_uint2(*reinterpret_cast<uint32_t*>(&h01),
                           *reinterpret_cast<uint32_t*>(&h23));
        }
    }
    // first loop barrier publishes A stores + stage-0 data

    // per-thread lane-constant addressing
    const int rowA0 = wm*32 + (lane & 15);
    const int ra7   = rowA0 & 7;
    const uint32_t aRow0 = su + OFF_A + (uint32_t)rowA0 * (KTOT*2);
    const uint32_t aRow1 = aRow0 + 16u * (KTOT*2);
    const int k8a   = (lane >> 4) * 8;
    // W ldmatrix rows for 2 n16-groups (32 n per warp), SW64 on 64B rows.
    const int nwl = ((lane >> 4) << 3) + (lane & 7);
    const uint32_t kb2 = ((uint32_t)((lane >> 3) & 1)) * 16u;
    uint32_t swb[2];
    #pragma unroll
    for (int g = 0; g < 2; g++) {
        uint32_t o = (uint32_t)(wn*32 + g*16 + nwl) * 64u + kb2;
        swb[g] = o ^ ((o >> 3) & 0x30u);
    }

    // epilogue rows: 4 per thread; per-row bias pointer (L2 reads, no smem)
    const int rb = wm*32 + (lane >> 2);
    int rr[4]; const float* bq[4];
    #pragma unroll
    for (int q = 0; q < 4; q++) {
        rr[q] = rb + (q & 1)*8 + (q >> 1)*16;
        int sel = ((mBase + rr[q]) / SS != b0) ? 1 : 0;
        bq[q] = bias + (size_t)(sel ? b1 : b0) * NTOT;
    }

    float pr[4] = {0.f, 0.f, 0.f, 0.f};
    int ch = 0;
    int stComp = 0;                 // stage of chunk ch
    int stIss  = NSTAGE - 1;        // stage for next issue

    for (int nt = 0; nt < NTILES; nt++) {
        float c[2][4][4];
        #pragma unroll
        for (int mi = 0; mi < 2; mi++)
            #pragma unroll
            for (int g = 0; g < 4; g++)
                #pragma unroll
                for (int j = 0; j < 4; j++) c[mi][g][j] = 0.f;

        for (int kc = 0; kc < KCHUNKS; kc++, ch++) {
            // wait for chunk ch (immediate-operand forms, tail-tightened)
            if (NSTAGE == 5) {
                if (ch < TOTAL-3)       { asm volatile("cp.async.wait_group 3;" ::: "memory"); }
                else if (ch == TOTAL-3) { asm volatile("cp.async.wait_group 2;" ::: "memory"); }
                else if (ch == TOTAL-2) { asm volatile("cp.async.wait_group 1;" ::: "memory"); }
                else                    { asm volatile("cp.async.wait_group 0;" ::: "memory"); }
            } else {
                if (ch < TOTAL-2)       { asm volatile("cp.async.wait_group 2;" ::: "memory"); }
                else if (ch == TOTAL-2) { asm volatile("cp.async.wait_group 1;" ::: "memory"); }
                else                    { asm volatile("cp.async.wait_group 0;" ::: "memory"); }
            }
            __syncthreads();   // publishes chunk ch; proves ch-1 fully read
            if (ch + NSTAGE - 1 < TOTAL) {
                issue(ch + NSTAGE - 1, stIss);
                stIss++; if (stIss == NSTAGE) stIss = 0;
            }

            const uint32_t Wb = su + OFFW + (uint32_t)stComp * 8192u;
            stComp++; if (stComp == NSTAGE) stComp = 0;

            #pragma unroll
            for (int ks = 0; ks < 2; ks++) {
                int kk = kc*32 + ks*16 + k8a;
                uint32_t aoff = (uint32_t)(((kk >> 3) ^ ra7) << 4);
                uint32_t a00,a01,a02,a03, a10,a11,a12,a13;
                ldsm4(a00,a01,a02,a03, aRow0 + aoff);
                ldsm4(a10,a11,a12,a13, aRow1 + aoff);

                uint32_t b00,b01,b02,b03, b10,b11,b12,b13;
                ldsm4(b00,b01,b02,b03, Wb + (swb[0] ^ ((uint32_t)ks * 32u)));
                ldsm4(b10,b11,b12,b13, Wb + (swb[1] ^ ((uint32_t)ks * 32u)));

                mma_f16(c[0][0], a00,a01,a02,a03, b00,b01);
                mma_f16(c[0][1], a00,a01,a02,a03, b02,b03);
                mma_f16(c[0][2], a00,a01,a02,a03, b10,b11);
                mma_f16(c[0][3], a00,a01,a02,a03, b12,b13);
                mma_f16(c[1][0], a10,a11,a12,a13, b00,b01);
                mma_f16(c[1][1], a10,a11,a12,a13, b02,b03);
                mma_f16(c[1][2], a10,a11,a12,a13, b10,b11);
                mma_f16(c[1][3], a10,a11,a12,a13, b12,b13);
            }
        }

        // epilogue for this 128-col n-tile (bias from L2)
        int nbb = nt*128 + wn*32;
        #pragma unroll
        for (int g = 0; g < 4; g++) {
            int n0 = nbb + (g & 1)*8 + (g >> 1)*16 + (lane & 3)*2;
            float v0 = vs[n0], v1 = vs[n0+1];
            #pragma unroll
            for (int mi = 0; mi < 2; mi++) {
                int q0 = mi*2;
                pr[q0]   += v0 * fast_tanh(c[mi][g][0] + __ldg(bq[q0]   + n0))
                          + v1 * fast_tanh(c[mi][g][1] + __ldg(bq[q0]   + n0 + 1));
                pr[q0+1] += v0 * fast_tanh(c[mi][g][2] + __ldg(bq[q0+1] + n0))
                          + v1 * fast_tanh(c[mi][g][3] + __ldg(bq[q0+1] + n0 + 1));
            }
        }
    }

    // reduce quad, then combine the 4 n-warp banks
    #pragma unroll
    for (int q = 0; q < 4; q++) {
        pr[q] += __shfl_xor_sync(0xffffffffu, pr[q], 1);
        pr[q] += __shfl_xor_sync(0xffffffffu, pr[q], 2);
    }
    if ((lane & 3) == 0) {
        #pragma unroll
        for (int q = 0; q < 4; q++) scp[wn*64 + rr[q]] = pr[q];
    }
    __syncthreads();
    if (tid < 64)
        outS[mBase + tid] = scp[tid] + scp[64 + tid] + scp[128 + tid] + scp[192 + tid];
}

// ---------------------------------------------------------------------------
// Weight conversion to fp16, transposed to [N][K] k-contiguous
// ---------------------------------------------------------------------------
__global__ void k_convW(const float* __restrict__ attnW, const float* __restrict__ decW)
{
    int i = blockIdx.x * 256 + threadIdx.x;
    if (i < 768*512) {
        int j = i / 512, k = i % 512;
        g_W1[i] = __float2half_rn(attnW[j*768 + k]);
    } else {
        int i2 = i - 768*512;
        int j = i2 / 256, k = i2 % 256;
        g_W2[i2] = __float2half_rn(decW[j*512 + k]);
    }
}

// ---------------------------------------------------------------------------
// K1: embed + GRU cell + attention hidden-part bias (merged)
// ---------------------------------------------------------------------------
__global__ void k_gru(const float* __restrict__ din, const float* __restrict__ lasth,
                      const float* __restrict__ embW, const float* __restrict__ embB,
                      const float* __restrict__ Wih, const float* __restrict__ Whh,
                      const float* __restrict__ bih, const float* __restrict__ bhh,
                      const float* __restrict__ attnW,
                      float* __restrict__ outHidden)
{
    __shared__ float emb[HH], hp[HH], gx[3*HH], gh[3*HH], hs[HH];
    int b = blockIdx.x, t = threadIdx.x;
    float d0 = din[b*2+0], d1 = din[b*2+1];
    emb[t] = d0*embW[t*2+0] + d1*embW[t*2+1] + embB[t];
    hp[t]  = lasth[b*HH + t];
    __syncthreads();
    int warp = t >> 5, lane = t & 31;
    for (int j = warp; j < 3*HH; j += 8) {
        const float* wi = Wih + (size_t)j*HH;
        const float* wh = Whh + (size_t)j*HH;
        float sx = 0.f, sh = 0.f;
        #pragma unroll
        for (int i = 0; i < 8; i++) {
            int k = lane + 32*i;
            sx += wi[k]*emb[k]; sh += wh[k]*hp[k];
        }
        #pragma unroll
        for (int o = 16; o; o >>= 1) {
            sx += __shfl_xor_sync(0xffffffffu, sx, o);
            sh += __shfl_xor_sync(0xffffffffu, sh, o);
        }
        if (lane == 0) { gx[j] = sx + bih[j]; gh[j] = sh + bhh[j]; }
    }
    __syncthreads();
    float r = sigmoidf_(gx[t]        + gh[t]);
    float z = sigmoidf_(gx[HH + t]   + gh[HH + t]);
    float n = tanhf    (gx[2*HH + t] + r*gh[2*HH + t]);
    float h = (1.0f - z)*n + z*hp[t];
    g_hnew[b*HH + t]    = h;
    outHidden[b*HH + t] = h;
    hs[t] = h;
    __syncthreads();
    for (int j = warp; j < 3*HH; j += 8) {
        const float* w = attnW + (size_t)j*(3*HH) + 2*HH;
        float s = 0.f;
        #pragma unroll
        for (int i = 0; i < 8; i++) { int k = lane + 32*i; s += w[k]*hs[k]; }
        #pragma unroll
        for (int o = 16; o; o >>= 1) s += __shfl_xor_sync(0xffffffffu, s, o);
        if (lane == 0) g_ph[b*(3*HH) + j] = s;
    }
}

__device__ __forceinline__ float blockReduce(float val, float* red, bool isMax)
{
    __syncthreads();
    int lane = threadIdx.x & 31, w = threadIdx.x >> 5;
    #pragma unroll
    for (int o = 16; o; o >>= 1) {
        float u = __shfl_xor_sync(0xffffffffu, val, o);
        val = isMax ? fmaxf(val, u) : val + u;
    }
    if (lane == 0) red[w] = val;
    __syncthreads();
    if (w == 0) {
        val = (lane < 8) ? red[lane] : (isMax ? -1e30f : 0.f);
        #pragma unroll
        for (int o = 16; o; o >>= 1) {
            float u = __shfl_xor_sync(0xffffffffu, val, o);
            val = isMax ? fmaxf(val, u) : val + u;
        }
        if (lane == 0) red[0] = val;
    }
    __syncthreads();
    return red[0];
}

// ---------------------------------------------------------------------------
// K3: softmax (recomputed locally) + context partial. grid (B, 8).
// ---------------------------------------------------------------------------
__global__ void k_ctx(const float* __restrict__ stat)
{
    __shared__ float at[SS];
    __shared__ float red[32];
    int b = blockIdx.x, p = blockIdx.y, t = threadIdx.x;

    float mx = -1e30f;
    for (int s = t; s < SS; s += 256) { float x = g_scores[b*SS+s]; at[s]=x; mx=fmaxf(mx,x); }
    mx = blockReduce(mx, red, true);
    float sum = 0.f;
    for (int s = t; s < SS; s += 256) { float e = __expf(at[s]-mx); at[s]=e; sum+=e; }
    sum = blockReduce(sum, red, false);
    float inv = 1.0f / sum;

    int s0 = p * 125;
    const float* sb = stat + ((size_t)b*SS + s0)*HH;
    float acc = 0.f;
    #pragma unroll 8
    for (int s = 0; s < 125; s++) acc += at[s0 + s]*sb[(size_t)s*HH + t];
    g_ctxp[(b*8 + p)*HH + t] = acc * inv;
}

// combine partials + pointer ctx-part bias
__global__ void k_pc(const float* __restrict__ decW)
{
    __shared__ float ctx[HH];
    int b = blockIdx.x, t = threadIdx.x;
    float acc = 0.f;
    #pragma unroll
    for (int p = 0; p < 8; p++) acc += g_ctxp[(b*8 + p)*HH + t];
    ctx[t] = acc;
    __syncthreads();
    int warp = t >> 5, lane = t & 31;
    for (int j = warp; j < 2*HH; j += 8) {
        const float* w = decW + (size_t)j*(2*HH) + HH;
        float s = 0.f;
        #pragma unroll
        for (int i = 0; i < 8; i++) { int k = lane + 32*i; s += w[k]*ctx[k]; }
        #pragma unroll
        for (int o = 16; o; o >>= 1) s += __shfl_xor_sync(0xffffffffu, s, o);
        if (lane == 0) g_pc[b*(2*HH) + j] = s;
    }
}

// final softmax into d_out[0 : B*S)
__global__ void k_out(float* __restrict__ out)
{
    __shared__ float at[SS];
    __shared__ float red[32];
    int b = blockIdx.x, t = threadIdx.x;
    float mx = -1e30f;
    for (int s = t; s < SS; s += 256) { float x = g_scores2[b*SS+s]; at[s]=x; mx=fmaxf(mx,x); }
    mx = blockReduce(mx, red, true);
    float sum = 0.f;
    for (int s = t; s < SS; s += 256) { float e = expf(at[s]-mx); at[s]=e; sum+=e; }
    sum = blockReduce(sum, red, false);
    float inv = 1.0f/sum;
    for (int s = t; s < SS; s += 256) out[b*SS+s] = at[s]*inv;
}

// ---------------------------------------------------------------------------
extern "C" void kernel_launch(void* const* d_in, const int* in_sizes, int n_in,
                              void* d_out, int out_size)
{
    (void)in_sizes; (void)n_in; (void)out_size;
    const float* din   = (const float*)d_in[0];
    const float* lasth = (const float*)d_in[1];
    const float* stat  = (const float*)d_in[2];
    const float* dyn   = (const float*)d_in[3];
    const float* embW  = (const float*)d_in[4];
    const float* embB  = (const float*)d_in[5];
    const float* Wih   = (const float*)d_in[6];
    const float* Whh   = (const float*)d_in[7];
    const float* bih   = (const float*)d_in[8];
    const float* bhh   = (const float*)d_in[9];
    const float* attnW = (const float*)d_in[10];
    const float* attnV = (const float*)d_in[11];
    const float* decW  = (const float*)d_in[12];
    const float* decV  = (const float*)d_in[13];
    float* out = (float*)d_out;

    // GEMM1: 5 stages, occ 2: 4096 + 65536 + 40960 = 110592 (2x <= 228KB)
    // GEMM2: 4 stages, occ 3: 4096 + 32768 + 32768 =  69632 (3x <= 228KB)
    const int smem1 = OFF_A + (64*512*2) + 5*8192;
    const int smem2 = OFF_A + (64*256*2) + 4*8192;
    cudaFuncSetAttribute((const void*)score_gemm_mma<768,512,0,5,2>,
                         cudaFuncAttributeMaxDynamicSharedMemorySize, smem1);
    cudaFuncSetAttribute((const void*)score_gemm_mma<512,256,1,4,3>,
                         cudaFuncAttributeMaxDynamicSharedMemorySize, smem2);

    k_convW<<<2048, 256>>>(attnW, decW);
    k_gru<<<BB, 256>>>(din, lasth, embW, embB, Wih, Whh, bih, bhh, attnW, out + MM);
    score_gemm_mma<768,512,0,5,2><<<MM/64, 256, smem1>>>(stat, dyn, attnV);
    k_ctx<<<dim3(BB, 8), 256>>>(stat);
    k_pc<<<BB, 256>>>(decW);
    score_gemm_mma<512,256,1,4,3><<<MM/64, 256, smem2>>>(stat, stat, decV);
    k_out<<<BB, 256>>>(out);
}

// round 17
// speedup vs baseline: 1.0313x; 1.0312x over previous
#include <cuda_runtime.h>
#include <cuda_fp16.h>
#include <cstdint>
#include <math.h>

#define BB 128
#define SS 1000
#define HH 256
#define MM (BB*SS)        // 128000

// ------------------------- device scratch (no allocs) -----------------------
__device__ float g_hnew[BB*HH];
__device__ float g_ph[BB*3*HH];           // attention hidden-part bias [B,768]
__device__ float g_scores[MM];
__device__ float g_ctxp[BB*8*HH];         // context partials
__device__ float g_pc[BB*2*HH];           // pointer ctx-part bias [B,512]
__device__ float g_scores2[MM];
__device__ __half g_W1[768*512];          // attn_W cols [0,512), fp16, [N][K]
__device__ __half g_W2[512*256];          // dec_W  cols [0,256), fp16, [N][K]

__device__ __forceinline__ float sigmoidf_(float x){ return 1.0f/(1.0f+expf(-x)); }

__device__ __forceinline__ float fast_tanh(float x){
    x = fminf(fmaxf(x, -15.0f), 15.0f);
    float e = __expf(2.0f*x);
    return __fdividef(e - 1.0f, e + 1.0f);
}

__device__ __forceinline__ uint32_t smem_to_u32(const void* p) {
    uint32_t a;
    asm("{ .reg .u64 t; cvta.to.shared.u64 t, %1; cvt.u32.u64 %0, t; }" : "=r"(a) : "l"(p));
    return a;
}

__device__ __forceinline__ void ldsm4(uint32_t& r0, uint32_t& r1, uint32_t& r2, uint32_t& r3,
                                      uint32_t addr) {
    asm volatile("ldmatrix.sync.aligned.m8n8.x4.shared.b16 {%0,%1,%2,%3}, [%4];"
                 : "=r"(r0), "=r"(r1), "=r"(r2), "=r"(r3) : "r"(addr));
}

__device__ __forceinline__ void mma_f16(float* c, uint32_t a0, uint32_t a1, uint32_t a2,
                                        uint32_t a3, uint32_t b0, uint32_t b1) {
    asm volatile(
        "mma.sync.aligned.m16n8k16.row.col.f32.f16.f16.f32 "
        "{%0,%1,%2,%3},{%4,%5,%6,%7},{%8,%9},{%0,%1,%2,%3};"
        : "+f"(c[0]), "+f"(c[1]), "+f"(c[2]), "+f"(c[3])
        : "r"(a0), "r"(a1), "r"(a2), "r"(a3), "r"(b0), "r"(b1));
}

__device__ __forceinline__ void cpasync16(uint32_t dst, const void* src) {
    asm volatile("cp.async.cg.shared.global [%0], [%1], 16;" :: "r"(dst), "l"(src));
}

// SMEM layout (dynamic, byte offsets)
#define OFF_V   0                         // NTOT floats
#define OFF_B   3072                      // 2*NTOT floats
#define OFF_SC  9216                      // 256 floats (4 n-warp partial banks)
#define OFF_A   10240                     // A fp16, 64*KTOT*2 bytes

// ---------------------------------------------------------------------------
// Fused score GEMM on HMMA (mma.sync fp16, single-term) — R12 compute core
// with a 4-stage, distance-3 cp.async pipeline (128n x 32k chunks, 8KB/stage,
// SW64 rows) and ONE __syncthreads per chunk:
//   score[m] = sum_n v[n] * tanh( sum_k A[m,k]*W[n,k] + bias[b(m),n] )
// BM=64/CTA, 8 warps (2m x 4n), warp tile 32m x 32n, occ 2 (GEMM2: occ 3).
// ---------------------------------------------------------------------------
template<int NTOT, int KTOT, int SEL>
__global__ void __launch_bounds__(256, SEL ? 3 : 2) score_gemm_mma(
    const float* __restrict__ A1, const float* __restrict__ A2,
    const float* __restrict__ v)
{
    constexpr int NTILES  = NTOT / 128;
    constexpr int KCHUNKS = KTOT / 32;           // 32k per chunk
    constexpr int TOTAL   = NTILES * KCHUNKS;
    constexpr int ASZ     = 64 * KTOT * 2;       // A bytes (fp16)
    constexpr int OFFW    = OFF_A + ASZ;         // W ring: 4 x 8KB

    const __half* __restrict__ Wp  = SEL ? g_W2 : g_W1;
    const float* __restrict__ bias = SEL ? g_pc : g_ph;
    float* __restrict__ outS       = SEL ? g_scores2 : g_scores;

    extern __shared__ char smem[];
    const uint32_t su = smem_to_u32(smem);
    float* vs  = (float*)(smem + OFF_V);
    float* bsm = (float*)(smem + OFF_B);
    float* scp = (float*)(smem + OFF_SC);

    const int tid  = threadIdx.x;
    const int lane = tid & 31;
    const int wrp  = tid >> 5;
    const int wm   = wrp & 1;          // m-half (32 rows)
    const int wn   = wrp >> 1;         // n-quarter (32 cols of the 128 tile)
    const int mBase = blockIdx.x * 64;
    const int b0 = mBase / SS;
    const int b1 = (mBase + 63) / SS;

    // --- W chunk issuer: 128n x 32k fp16, 64B rows, SW64, via cp.async (8KB) ---
    auto issue = [&](int chunk) {
        int nt = chunk / KCHUNKS, kc = chunk - nt*KCHUNKS;
        uint32_t dst = su + OFFW + (uint32_t)(chunk & 3) * 8192u;
        int nb = nt * 128, kb = kc * 32;
        #pragma unroll
        for (int i = 0; i < 2; i++) {
            int id = tid*2 + i;            // 0..511
            int n  = id >> 2, kseg = id & 3;
            uint32_t o  = (uint32_t)n * 64u + (uint32_t)kseg * 16u;
            uint32_t sw = o ^ ((o >> 3) & 0x30u);
            cpasync16(dst + sw, Wp + (size_t)(nb + n) * KTOT + kb + kseg*8);
        }
        asm volatile("cp.async.commit_group;" ::: "memory");
    };

    // prime 3 stages, overlapping with A conversion below
    issue(0); issue(1); issue(2);

    // v and bias rows into smem
    for (int i = tid; i < NTOT; i += 256) vs[i] = v[i];
    for (int i = tid; i < 2*NTOT; i += 256) {
        int bi = i / NTOT, n = i - bi*NTOT;
        bsm[i] = bias[(bi ? b1 : b0) * NTOT + n];
    }

    // --- convert A (fp32) -> fp16 into SW128-swizzled smem, full K ---
    {
        constexpr int K4 = KTOT / 4;
        constexpr int ITERS = 64 * K4 / 256;
        #pragma unroll
        for (int it = 0; it < ITERS; it++) {
            int id  = it*256 + tid;
            int row = id / K4;
            int k   = (id - row*K4) * 4;
            const float* src;
            if (KTOT > 256 && k >= 256) src = A2 + (size_t)(mBase + row)*HH + (k - 256);
            else                        src = A1 + (size_t)(mBase + row)*HH + k;
            float4 a4 = *reinterpret_cast<const float4*>(src);
            __half2 h01 = __floats2half2_rn(a4.x, a4.y);
            __half2 h23 = __floats2half2_rn(a4.z, a4.w);
            uint32_t sw = ((uint32_t)(((k >> 3) ^ (row & 7)) << 4)) + ((uint32_t)(k & 4) << 1);
            uint32_t ro = (uint32_t)row * (KTOT*2);
            *reinterpret_cast<uint2*>(smem + OFF_A + ro + sw) =
                make_uint2(*reinterpret_cast<uint32_t*>(&h01),
                           *reinterpret_cast<uint32_t*>(&h23));
        }
    }
    // NOTE: no standalone barrier — the first loop iteration's barrier
    // publishes both the A stores and the stage-0 cp.async data.

    // per-thread lane-constant addressing
    const int rowA0 = wm*32 + (lane & 15);            // A ldsm row, mi=0
    const int ra7   = rowA0 & 7;                      // (rowA0+16) & 7 identical
    const uint32_t aRow0 = su + OFF_A + (uint32_t)rowA0 * (KTOT*2);
    const uint32_t aRow1 = aRow0 + 16u * (KTOT*2);
    const int k8a   = (lane >> 4) * 8;
    // W ldmatrix rows for 2 n16-groups (32 n per warp), SW64 on 64B rows.
    // Base swizzled at ks=0; per-ks adjust = XOR ks*32 (base bit 5 is 0;
    // the SW64 mask depends only on row bits, unchanged by the XOR).
    const int nwl = ((lane >> 4) << 3) + (lane & 7);  // 0..15 row-within-16
    const uint32_t kb2 = ((uint32_t)((lane >> 3) & 1)) * 16u;   // k8 -> 16B
    uint32_t swb[2];
    #pragma unroll
    for (int g = 0; g < 2; g++) {
        uint32_t o = (uint32_t)(wn*32 + g*16 + nwl) * 64u + kb2;
        swb[g] = o ^ ((o >> 3) & 0x30u);
    }

    // epilogue rows: 4 per thread (2 per m16 frag x 2 frags)
    const int rb = wm*32 + (lane >> 2);
    int rr[4]; int selr[4];
    #pragma unroll
    for (int q = 0; q < 4; q++) {
        rr[q] = rb + (q & 1)*8 + (q >> 1)*16;         // {rb, rb+8, rb+16, rb+24}
        selr[q] = ((mBase + rr[q]) / SS != b0) ? 1 : 0;
    }

    float pr[4] = {0.f, 0.f, 0.f, 0.f};
    int ch = 0;

    for (int nt = 0; nt < NTILES; nt++) {
        // c[mi][g][4]: mi = m16 frag (0,1), g = n8 block (0..3)
        float c[2][4][4];
        #pragma unroll
        for (int mi = 0; mi < 2; mi++)
            #pragma unroll
            for (int g = 0; g < 4; g++)
                #pragma unroll
                for (int j = 0; j < 4; j++) c[mi][g][j] = 0.f;

        for (int kc = 0; kc < KCHUNKS; kc++, ch++) {
            if (ch < TOTAL-2)      { asm volatile("cp.async.wait_group 2;" ::: "memory"); }
            else if (ch == TOTAL-2){ asm volatile("cp.async.wait_group 1;" ::: "memory"); }
            else                   { asm volatile("cp.async.wait_group 0;" ::: "memory"); }
            __syncthreads();   // publishes chunk ch; proves chunk ch-1 fully read
            if (ch + 3 < TOTAL) issue(ch + 3);

            const uint32_t Wb = su + OFFW + (uint32_t)(ch & 3) * 8192u;

            #pragma unroll
            for (int ks = 0; ks < 2; ks++) {
                int kk = kc*32 + ks*16 + k8a;
                uint32_t aoff = (uint32_t)(((kk >> 3) ^ ra7) << 4);
                uint32_t a00,a01,a02,a03, a10,a11,a12,a13;
                ldsm4(a00,a01,a02,a03, aRow0 + aoff);
                ldsm4(a10,a11,a12,a13, aRow1 + aoff);

                uint32_t b00,b01,b02,b03, b10,b11,b12,b13;
                ldsm4(b00,b01,b02,b03, Wb + (swb[0] ^ ((uint32_t)ks * 32u)));
                ldsm4(b10,b11,b12,b13, Wb + (swb[1] ^ ((uint32_t)ks * 32u)));

                mma_f16(c[0][0], a00,a01,a02,a03, b00,b01);
                mma_f16(c[0][1], a00,a01,a02,a03, b02,b03);
                mma_f16(c[0][2], a00,a01,a02,a03, b10,b11);
                mma_f16(c[0][3], a00,a01,a02,a03, b12,b13);
                mma_f16(c[1][0], a10,a11,a12,a13, b00,b01);
                mma_f16(c[1][1], a10,a11,a12,a13, b02,b03);
                mma_f16(c[1][2], a10,a11,a12,a13, b10,b11);
                mma_f16(c[1][3], a10,a11,a12,a13, b12,b13);
            }
            // no second barrier: stage reuse is protected by the next
            // iteration's barrier (4-stage ring, distance-3 prefetch)
        }

        // epilogue for this 128-col n-tile
        int nbb = nt*128 + wn*32;
        #pragma unroll
        for (int g = 0; g < 4; g++) {
            int n0 = nbb + (g & 1)*8 + (g >> 1)*16 + (lane & 3)*2;
            float v0 = vs[n0], v1 = vs[n0+1];
            #pragma unroll
            for (int mi = 0; mi < 2; mi++) {
                int q0 = mi*2;
                pr[q0]   += v0 * fast_tanh(c[mi][g][0] + bsm[selr[q0]*NTOT + n0])
                          + v1 * fast_tanh(c[mi][g][1] + bsm[selr[q0]*NTOT + n0 + 1]);
                pr[q0+1] += v0 * fast_tanh(c[mi][g][2] + bsm[selr[q0+1]*NTOT + n0])
                          + v1 * fast_tanh(c[mi][g][3] + bsm[selr[q0+1]*NTOT + n0 + 1]);
            }
        }
    }

    // reduce quad (lanes sharing a row), then combine the 4 n-warp banks
    #pragma unroll
    for (int q = 0; q < 4; q++) {
        pr[q] += __shfl_xor_sync(0xffffffffu, pr[q], 1);
        pr[q] += __shfl_xor_sync(0xffffffffu, pr[q], 2);
    }
    if ((lane & 3) == 0) {
        #pragma unroll
        for (int q = 0; q < 4; q++) scp[wn*64 + rr[q]] = pr[q];
    }
    __syncthreads();
    if (tid < 64)
        outS[mBase + tid] = scp[tid] + scp[64 + tid] + scp[128 + tid] + scp[192 + tid];
}

// ---------------------------------------------------------------------------
// Weight conversion to fp16, transposed to [N][K] k-contiguous
// ---------------------------------------------------------------------------
__global__ void k_convW(const float* __restrict__ attnW, const float* __restrict__ decW)
{
    int i = blockIdx.x * 256 + threadIdx.x;
    if (i < 768*512) {
        int j = i / 512, k = i % 512;
        g_W1[i] = __float2half_rn(attnW[j*768 + k]);
    } else {
        int i2 = i - 768*512;
        int j = i2 / 256, k = i2 % 256;
        g_W2[i2] = __float2half_rn(decW[j*512 + k]);
    }
}

// ---------------------------------------------------------------------------
// K1: embed + GRU cell + attention hidden-part bias (merged)
// ---------------------------------------------------------------------------
__global__ void k_gru(const float* __restrict__ din, const float* __restrict__ lasth,
                      const float* __restrict__ embW, const float* __restrict__ embB,
                      const float* __restrict__ Wih, const float* __restrict__ Whh,
                      const float* __restrict__ bih, const float* __restrict__ bhh,
                      const float* __restrict__ attnW,
                      float* __restrict__ outHidden)
{
    __shared__ float emb[HH], hp[HH], gx[3*HH], gh[3*HH], hs[HH];
    int b = blockIdx.x, t = threadIdx.x;
    float d0 = din[b*2+0], d1 = din[b*2+1];
    emb[t] = d0*embW[t*2+0] + d1*embW[t*2+1] + embB[t];
    hp[t]  = lasth[b*HH + t];
    __syncthreads();
    int warp = t >> 5, lane = t & 31;
    for (int j = warp; j < 3*HH; j += 8) {
        const float* wi = Wih + (size_t)j*HH;
        const float* wh = Whh + (size_t)j*HH;
        float sx = 0.f, sh = 0.f;
        #pragma unroll
        for (int i = 0; i < 8; i++) {
            int k = lane + 32*i;
            sx += wi[k]*emb[k]; sh += wh[k]*hp[k];
        }
        #pragma unroll
        for (int o = 16; o; o >>= 1) {
            sx += __shfl_xor_sync(0xffffffffu, sx, o);
            sh += __shfl_xor_sync(0xffffffffu, sh, o);
        }
        if (lane == 0) { gx[j] = sx + bih[j]; gh[j] = sh + bhh[j]; }
    }
    __syncthreads();
    float r = sigmoidf_(gx[t]        + gh[t]);
    float z = sigmoidf_(gx[HH + t]   + gh[HH + t]);
    float n = tanhf    (gx[2*HH + t] + r*gh[2*HH + t]);
    float h = (1.0f - z)*n + z*hp[t];
    g_hnew[b*HH + t]    = h;
    outHidden[b*HH + t] = h;
    hs[t] = h;
    __syncthreads();
    for (int j = warp; j < 3*HH; j += 8) {
        const float* w = attnW + (size_t)j*(3*HH) + 2*HH;
        float s = 0.f;
        #pragma unroll
        for (int i = 0; i < 8; i++) { int k = lane + 32*i; s += w[k]*hs[k]; }
        #pragma unroll
        for (int o = 16; o; o >>= 1) s += __shfl_xor_sync(0xffffffffu, s, o);
        if (lane == 0) g_ph[b*(3*HH) + j] = s;
    }
}

__device__ __forceinline__ float blockReduce(float val, float* red, bool isMax)
{
    __syncthreads();
    int lane = threadIdx.x & 31, w = threadIdx.x >> 5;
    #pragma unroll
    for (int o = 16; o; o >>= 1) {
        float u = __shfl_xor_sync(0xffffffffu, val, o);
        val = isMax ? fmaxf(val, u) : val + u;
    }
    if (lane == 0) red[w] = val;
    __syncthreads();
    if (w == 0) {
        val = (lane < 8) ? red[lane] : (isMax ? -1e30f : 0.f);
        #pragma unroll
        for (int o = 16; o; o >>= 1) {
            float u = __shfl_xor_sync(0xffffffffu, val, o);
            val = isMax ? fmaxf(val, u) : val + u;
        }
        if (lane == 0) red[0] = val;
    }
    __syncthreads();
    return red[0];
}

// ---------------------------------------------------------------------------
// K3: softmax (recomputed locally) + context partial. grid (B, 8).
// ---------------------------------------------------------------------------
__global__ void k_ctx(const float* __restrict__ stat)
{
    __shared__ float at[SS];
    __shared__ float red[32];
    int b = blockIdx.x, p = blockIdx.y, t = threadIdx.x;

    float mx = -1e30f;
    for (int s = t; s < SS; s += 256) { float x = g_scores[b*SS+s]; at[s]=x; mx=fmaxf(mx,x); }
    mx = blockReduce(mx, red, true);
    float sum = 0.f;
    for (int s = t; s < SS; s += 256) { float e = __expf(at[s]-mx); at[s]=e; sum+=e; }
    sum = blockReduce(sum, red, false);
    float inv = 1.0f / sum;

    int s0 = p * 125;
    const float* sb = stat + ((size_t)b*SS + s0)*HH;
    float acc = 0.f;
    #pragma unroll 8
    for (int s = 0; s < 125; s++) acc += at[s0 + s]*sb[(size_t)s*HH + t];
    g_ctxp[(b*8 + p)*HH + t] = acc * inv;
}

// combine partials + pointer ctx-part bias
__global__ void k_pc(const float* __restrict__ decW)
{
    __shared__ float ctx[HH];
    int b = blockIdx.x, t = threadIdx.x;
    float acc = 0.f;
    #pragma unroll
    for (int p = 0; p < 8; p++) acc += g_ctxp[(b*8 + p)*HH + t];
    ctx[t] = acc;
    __syncthreads();
    int warp = t >> 5, lane = t & 31;
    for (int j = warp; j < 2*HH; j += 8) {
        const float* w = decW + (size_t)j*(2*HH) + HH;
        float s = 0.f;
        #pragma unroll
        for (int i = 0; i < 8; i++) { int k = lane + 32*i; s += w[k]*ctx[k]; }
        #pragma unroll
        for (int o = 16; o; o >>= 1) s += __shfl_xor_sync(0xffffffffu, s, o);
        if (lane == 0) g_pc[b*(2*HH) + j] = s;
    }
}

// final softmax into d_out[0 : B*S)
__global__ void k_out(float* __restrict__ out)
{
    __shared__ float at[SS];
    __shared__ float red[32];
    int b = blockIdx.x, t = threadIdx.x;
    float mx = -1e30f;
    for (int s = t; s < SS; s += 256) { float x = g_scores2[b*SS+s]; at[s]=x; mx=fmaxf(mx,x); }
    mx = blockReduce(mx, red, true);
    float sum = 0.f;
    for (int s = t; s < SS; s += 256) { float e = __expf(at[s]-mx); at[s]=e; sum+=e; }
    sum = blockReduce(sum, red, false);
    float inv = 1.0f/sum;
    for (int s = t; s < SS; s += 256) out[b*SS+s] = at[s]*inv;
}

// ---------------------------------------------------------------------------
extern "C" void kernel_launch(void* const* d_in, const int* in_sizes, int n_in,
                              void* d_out, int out_size)
{
    (void)in_sizes; (void)n_in; (void)out_size;
    const float* din   = (const float*)d_in[0];
    const float* lasth = (const float*)d_in[1];
    const float* stat  = (const float*)d_in[2];
    const float* dyn   = (const float*)d_in[3];
    const float* embW  = (const float*)d_in[4];
    const float* embB  = (const float*)d_in[5];
    const float* Wih   = (const float*)d_in[6];
    const float* Whh   = (const float*)d_in[7];
    const float* bih   = (const float*)d_in[8];
    const float* bhh   = (const float*)d_in[9];
    const float* attnW = (const float*)d_in[10];
    const float* attnV = (const float*)d_in[11];
    const float* decW  = (const float*)d_in[12];
    const float* decV  = (const float*)d_in[13];
    float* out = (float*)d_out;

    // dynamic smem: OFF_A + ASZ + 4*8KB (R14 layout)
    const int smem1 = OFF_A + (64*512*2) + 32768;   // 108544 (occ 2)
    const int smem2 = OFF_A + (64*256*2) + 32768;   // 75776  (occ 3)
    cudaFuncSetAttribute(score_gemm_mma<768,512,0>,
                         cudaFuncAttributeMaxDynamicSharedMemorySize, smem1);
    cudaFuncSetAttribute(score_gemm_mma<512,256,1>,
                         cudaFuncAttributeMaxDynamicSharedMemorySize, smem2);

    k_convW<<<2048, 256>>>(attnW, decW);
    k_gru<<<BB, 256>>>(din, lasth, embW, embB, Wih, Whh, bih, bhh, attnW, out + MM);
    score_gemm_mma<768,512,0><<<MM/64, 256, smem1>>>(stat, dyn, attnV);
    k_ctx<<<dim3(BB, 8), 256>>>(stat);
    k_pc<<<BB, 256>>>(decW);
    score_gemm_mma<512,256,1><<<MM/64, 256, smem2>>>(stat, stat, decV);
    k_out<<<BB, 256>>>(out);
}